// round 4
// baseline (speedup 1.0000x reference)
#include <cuda_runtime.h>
#include <math.h>

// Problem constants
#define P_  4
#define FP_ 128
#define H_  512
#define C_  60
#define B_  256
#define T_  256
#define G3H 1536           // 3*H
#define NG  6144           // P*3H  (gate cols)
#define NJ  6656           // gate cols + output-gate cols
#define NTILES 416         // 4 M-tiles x 104 N-tiles of 64x64
#define NTILE_N 104
#define KG 640             // K for gate tiles  (512 h + 128 x_p)
#define KO 1024            // K for output tiles (512 h + 512 x_flat)

// ---------------- scratch (device globals; total ~180 MB) ----------------
__device__ float d_Xt[(size_t)T_ * B_ * 512];     // [t][b][p*128+f]  (134 MB)
__device__ float d_Wg0[P_ * KG * G3H];            // per part: [Wh_p ; Wx_p]
__device__ float d_Wg1[P_ * KG * G3H];
__device__ float d_Wo0[KO * H_];                  // [Who ; Wxo]
__device__ float d_Wo1[KO * H_];
__device__ float d_bias0[NJ];
__device__ float d_bias1[NJ];
__device__ float d_Z[(size_t)B_ * NJ];            // per-step pre-activations
__device__ float d_hstate[B_ * H_];
__device__ float d_cstate[B_ * P_ * H_];
__device__ unsigned d_gcnt;

__device__ __forceinline__ float sigf(float x) { return 1.0f / (1.0f + expf(-x)); }

// grid-wide barrier: fence, thread0 arrives + spins on L2 counter, block syncs.
__device__ __forceinline__ void gridsync(unsigned target) {
    __threadfence();
    __syncthreads();
    if (threadIdx.x == 0) {
        atomicAdd(&d_gcnt, 1u);
        volatile unsigned* c = &d_gcnt;
        while (*c < target) { __nanosleep(64); }
    }
    __syncthreads();
}

// ---------------- x transpose: Xt[t][b][p*128+f] = x[p][b][t][f] ----------------
__global__ void __launch_bounds__(256) transpose_x(const float* __restrict__ x,
                                                   float* __restrict__ Xt)
{
    size_t idx = (size_t)blockIdx.x * blockDim.x + threadIdx.x; // over P*B*T*32 float4
    if (idx >= (size_t)P_ * B_ * T_ * 32) return;
    int f4 = (int)(idx & 31);
    size_t r = idx >> 5;
    int t = (int)(r % T_);
    size_t r2 = r / T_;
    int b = (int)(r2 % B_);
    int p = (int)(r2 / B_);
    float4 v = ((const float4*)x)[idx];
    ((float4*)Xt)[(size_t)(t * B_ + b) * 128 + p * 32 + f4] = v;
}

// ---------------- persistent recurrent kernel ----------------
// 64x64 tiles. j0<6144: gate tile of part p (K=640: h then x_p)
//              j0>=6144: output-gate tile   (K=1024: h then x_flat)
__global__ void __launch_bounds__(256, 3) recurrent_kernel(int nblk)
{
    __shared__ float As[16][68];
    __shared__ float Bs[16][64];
    const int tid = threadIdx.x;
    const int tx = tid & 15, ty = tid >> 4;
    const int ar = tid >> 2, akq = (tid & 3) * 4;   // A-load: row ar, 4 cols at akq
    const int br = tid >> 4, bn = (tid & 15) * 4;   // B-load: row br, 4 cols at bn
    unsigned epoch = 0;

#pragma unroll 1
    for (int t = 0; t < T_; t++) {
#pragma unroll 1
        for (int l = 0; l < 2; l++) {
            const float* __restrict__ Wg   = l ? d_Wg1 : d_Wg0;
            const float* __restrict__ Wo   = l ? d_Wo1 : d_Wo0;
            const float* __restrict__ bias = l ? d_bias1 : d_bias0;
            const float* __restrict__ Xt = d_Xt + (size_t)t * (B_ * 512);

            // ---- GEMM phase over assigned tiles
#pragma unroll 1
            for (int tile = blockIdx.x; tile < NTILES; tile += nblk) {
                const int m0 = (tile / NTILE_N) * 64;
                const int j0 = (tile % NTILE_N) * 64;
                const bool isGate = (j0 < NG);
                const int p   = isGate ? (j0 / G3H) : 0;
                const int jc0 = isGate ? (j0 - p * G3H) : (j0 - NG);
                const float* Wmat = isGate ? (Wg + (size_t)p * KG * G3H + jc0)
                                           : (Wo + jc0);
                const int ldw  = isGate ? G3H : H_;
                const int Ktot = isGate ? KG : KO;
                const int xoff = isGate ? p * FP_ : 0;

                float acc[4][4];
#pragma unroll
                for (int i = 0; i < 4; i++)
#pragma unroll
                    for (int j = 0; j < 4; j++) acc[i][j] = 0.0f;

#pragma unroll 1
                for (int kb = 0; kb < Ktot; kb += 16) {
                    const int k = kb + akq;
                    float4 av;
                    if (k < H_)
                        av = __ldcg((const float4*)&d_hstate[(m0 + ar) * H_ + k]);
                    else
                        av = *(const float4*)&Xt[(m0 + ar) * 512 + xoff + (k - H_)];
                    As[akq + 0][ar] = av.x; As[akq + 1][ar] = av.y;
                    As[akq + 2][ar] = av.z; As[akq + 3][ar] = av.w;
                    *(float4*)&Bs[br][bn] =
                        *(const float4*)&Wmat[(size_t)(kb + br) * ldw + bn];
                    __syncthreads();
#pragma unroll
                    for (int kk = 0; kk < 16; kk++) {
                        float a[4], b[4];
#pragma unroll
                        for (int i = 0; i < 4; i++) a[i] = As[kk][ty * 4 + i];
#pragma unroll
                        for (int j = 0; j < 4; j++) b[j] = Bs[kk][tx * 4 + j];
#pragma unroll
                        for (int i = 0; i < 4; i++)
#pragma unroll
                            for (int j = 0; j < 4; j++) acc[i][j] += a[i] * b[j];
                    }
                    __syncthreads();
                }
#pragma unroll
                for (int i = 0; i < 4; i++) {
                    const int m = m0 + ty * 4 + i;
                    const int col = j0 + tx * 4;
                    float4 bv = *(const float4*)&bias[col];
                    float4 zv;
                    zv.x = acc[i][0] + bv.x; zv.y = acc[i][1] + bv.y;
                    zv.z = acc[i][2] + bv.z; zv.w = acc[i][3] + bv.w;
                    *(float4*)&d_Z[(size_t)m * NJ + col] = zv;
                }
            }
            epoch++; gridsync(epoch * (unsigned)nblk);

            // ---- elementwise LSTM update
            for (int idx = blockIdx.x * 256 + tid; idx < B_ * H_; idx += nblk * 256) {
                const int b = idx >> 9, hh = idx & (H_ - 1);
                const float* zr = d_Z + (size_t)b * NJ;
                float s = 0.0f;
#pragma unroll
                for (int p = 0; p < 4; p++) {
                    const int gb = p * G3H + hh;
                    float zi = __ldcg(zr + gb);
                    float zf = __ldcg(zr + gb + H_);
                    float zg = __ldcg(zr + gb + 2 * H_);
                    const int ci = ((b << 2) + p) * H_ + hh;
                    float cold = __ldcg(&d_cstate[ci]);
                    float cn = sigf(zf) * cold + sigf(zi) * tanhf(zg);
                    d_cstate[ci] = cn;
                    s += cn;
                }
                float o = sigf(__ldcg(zr + NG + hh));
                d_hstate[b * H_ + hh] = o * tanhf(s);
            }
            epoch++; gridsync(epoch * (unsigned)nblk);
        }
    }
}

// ---------------- classifier + log_softmax ----------------
__global__ void classifier(const float* __restrict__ Wfc, const float* __restrict__ bfc,
                           float* __restrict__ out)
{
    const int b = blockIdx.x;
    const int c = threadIdx.x;   // 64 threads
    __shared__ float sh[64];
    __shared__ float hrow[H_];
    for (int k = c; k < H_; k += 64) hrow[k] = d_hstate[b * H_ + k];
    __syncthreads();

    float z = -1e30f;
    if (c < C_) {
        z = bfc[c];
        for (int k = 0; k < H_; k++) z += hrow[k] * Wfc[k * C_ + c];
    }
    sh[c] = z; __syncthreads();
    for (int s = 32; s > 0; s >>= 1) {
        if (c < s) sh[c] = fmaxf(sh[c], sh[c + s]);
        __syncthreads();
    }
    const float mx = sh[0]; __syncthreads();
    float e = (c < C_) ? expf(z - mx) : 0.0f;
    sh[c] = e; __syncthreads();
    for (int s = 32; s > 0; s >>= 1) {
        if (c < s) sh[c] += sh[c + s];
        __syncthreads();
    }
    const float lse = logf(sh[0]) + mx;
    if (c < C_) out[b * C_ + c] = z - lse;
}

// ---------------- launch ----------------
extern "C" void kernel_launch(void* const* d_in, const int* in_sizes, int n_in,
                              void* d_out, int out_size)
{
    const float* x    = (const float*)d_in[0];
    const float* Wx1  = (const float*)d_in[1];
    const float* Wh1  = (const float*)d_in[2];
    const float* b1   = (const float*)d_in[3];
    const float* Wxo1 = (const float*)d_in[4];
    const float* Who1 = (const float*)d_in[5];
    const float* bo1  = (const float*)d_in[6];
    const float* Wx2  = (const float*)d_in[7];
    const float* Wh2  = (const float*)d_in[8];
    const float* b2   = (const float*)d_in[9];
    const float* Wxo2 = (const float*)d_in[10];
    const float* Who2 = (const float*)d_in[11];
    const float* bo2  = (const float*)d_in[12];
    const float* Wfc  = (const float*)d_in[13];
    const float* bfc  = (const float*)d_in[14];
    float* out = (float*)d_out;

    void *pxt, *pwg0, *pwg1, *pwo0, *pwo1, *pb0, *pb1, *ph, *pc, *pg;
    cudaGetSymbolAddress(&pxt, d_Xt);
    cudaGetSymbolAddress(&pwg0, d_Wg0);
    cudaGetSymbolAddress(&pwg1, d_Wg1);
    cudaGetSymbolAddress(&pwo0, d_Wo0);
    cudaGetSymbolAddress(&pwo1, d_Wo1);
    cudaGetSymbolAddress(&pb0, d_bias0);
    cudaGetSymbolAddress(&pb1, d_bias1);
    cudaGetSymbolAddress(&ph, d_hstate);
    cudaGetSymbolAddress(&pc, d_cstate);
    cudaGetSymbolAddress(&pg, d_gcnt);

    cudaMemsetAsync(ph, 0, sizeof(float) * B_ * H_);
    cudaMemsetAsync(pc, 0, sizeof(float) * B_ * P_ * H_);
    cudaMemsetAsync(pg, 0, sizeof(unsigned));

    // concat recurrent+input weights:  Wg[p] = [Wh_p (512x1536) ; Wx_p (128x1536)]
    for (int p = 0; p < P_; p++) {
        cudaMemcpyAsync((float*)pwg0 + (size_t)p * KG * G3H,
                        Wh1 + (size_t)p * H_ * G3H,
                        sizeof(float) * H_ * G3H, cudaMemcpyDeviceToDevice);
        cudaMemcpyAsync((float*)pwg0 + ((size_t)p * KG + H_) * G3H,
                        Wx1 + (size_t)p * FP_ * G3H,
                        sizeof(float) * FP_ * G3H, cudaMemcpyDeviceToDevice);
        cudaMemcpyAsync((float*)pwg1 + (size_t)p * KG * G3H,
                        Wh2 + (size_t)p * H_ * G3H,
                        sizeof(float) * H_ * G3H, cudaMemcpyDeviceToDevice);
        cudaMemcpyAsync((float*)pwg1 + ((size_t)p * KG + H_) * G3H,
                        Wx2 + (size_t)p * FP_ * G3H,
                        sizeof(float) * FP_ * G3H, cudaMemcpyDeviceToDevice);
    }
    // Wo = [Who (512x512) ; Wxo (512x512)]
    cudaMemcpyAsync(pwo0, Who1, sizeof(float) * H_ * H_, cudaMemcpyDeviceToDevice);
    cudaMemcpyAsync((float*)pwo0 + H_ * H_, Wxo1, sizeof(float) * H_ * H_,
                    cudaMemcpyDeviceToDevice);
    cudaMemcpyAsync(pwo1, Who2, sizeof(float) * H_ * H_, cudaMemcpyDeviceToDevice);
    cudaMemcpyAsync((float*)pwo1 + H_ * H_, Wxo2, sizeof(float) * H_ * H_,
                    cudaMemcpyDeviceToDevice);
    // bias = [b (P*1536) ; bo (512)]
    cudaMemcpyAsync(pb0, b1, sizeof(float) * NG, cudaMemcpyDeviceToDevice);
    cudaMemcpyAsync((float*)pb0 + NG, bo1, sizeof(float) * H_, cudaMemcpyDeviceToDevice);
    cudaMemcpyAsync(pb1, b2, sizeof(float) * NG, cudaMemcpyDeviceToDevice);
    cudaMemcpyAsync((float*)pb1 + NG, bo2, sizeof(float) * H_, cudaMemcpyDeviceToDevice);

    {
        size_t nf4 = (size_t)P_ * B_ * T_ * 32;
        transpose_x<<<(unsigned)((nf4 + 255) / 256), 256>>>(x, (float*)pxt);
    }

    // persistent grid sized to guaranteed co-residency
    int sms = 0, occ = 0;
    if (cudaDeviceGetAttribute(&sms, cudaDevAttrMultiProcessorCount, 0) != cudaSuccess
        || sms <= 0) sms = 148;
    if (cudaOccupancyMaxActiveBlocksPerMultiprocessor(&occ, recurrent_kernel, 256, 0)
        != cudaSuccess || occ <= 0) occ = 2;   // conservative fallback (kernel fits >=3)
    int nblk = sms * occ;
    if (nblk > NTILES) nblk = NTILES;
    recurrent_kernel<<<nblk, 256>>>(nblk);

    classifier<<<B_, 64>>>(Wfc, bfc, out);
}

// round 5
// speedup vs baseline: 1.8910x; 1.8910x over previous
#include <cuda_runtime.h>
#include <cuda_bf16.h>
#include <math.h>

// Problem constants
#define P_  4
#define FP_ 128
#define H_  512
#define C_  60
#define B_  256
#define T_  256
#define G3H 1536           // 3*H
#define NG  6144           // P*3H (gate cols)
#define NJ  6656           // gate cols + output-gate cols
#define KG  640            // K for gate tiles  (512 h + 128 x_p)
#define KO  1024           // K for output tiles (512 h + 512 x_flat)
#define TM  128            // CTA tile M
#define TN  64             // CTA tile N
#define KC  32             // k-chunk
#define NTILES 208         // (256/128) * (6656/64)
#define NTILE_N 104

typedef __nv_bfloat16 bf16;

// ---------------- device globals (~180 MB total) ----------------
__device__ bf16  d_XtH[(size_t)T_ * B_ * 512];   // x transposed, hi  (67 MB)
__device__ bf16  d_XtL[(size_t)T_ * B_ * 512];   // lo
__device__ bf16  d_WgH[2][(size_t)P_ * KG * G3H]; // per layer/part: [Wh_p ; Wx_p] hi
__device__ bf16  d_WgL[2][(size_t)P_ * KG * G3H];
__device__ bf16  d_WoH[2][KO * H_];               // [Who ; Wxo] hi
__device__ bf16  d_WoL[2][KO * H_];
__device__ float d_bias[2][NJ];
__device__ float d_Z[(size_t)B_ * NJ];
__device__ float d_hstate[B_ * H_];
__device__ bf16  d_hbH[B_ * H_];
__device__ bf16  d_hbL[B_ * H_];
__device__ float d_cstate[B_ * P_ * H_];
__device__ unsigned d_gcnt;

__device__ __forceinline__ float sigf(float x) { return 1.0f / (1.0f + expf(-x)); }

__device__ __forceinline__ void gridsync(unsigned target) {
    __threadfence();
    __syncthreads();
    if (threadIdx.x == 0) {
        atomicAdd(&d_gcnt, 1u);
        volatile unsigned* c = &d_gcnt;
        while (*c < target) { __nanosleep(32); }
    }
    __syncthreads();
}

__device__ __forceinline__ void ldsm4(unsigned& r0, unsigned& r1, unsigned& r2, unsigned& r3,
                                      unsigned addr) {
    asm volatile("ldmatrix.sync.aligned.m8n8.x4.shared.b16 {%0,%1,%2,%3},[%4];"
                 : "=r"(r0), "=r"(r1), "=r"(r2), "=r"(r3) : "r"(addr));
}
__device__ __forceinline__ void ldsm4t(unsigned& r0, unsigned& r1, unsigned& r2, unsigned& r3,
                                       unsigned addr) {
    asm volatile("ldmatrix.sync.aligned.m8n8.x4.trans.shared.b16 {%0,%1,%2,%3},[%4];"
                 : "=r"(r0), "=r"(r1), "=r"(r2), "=r"(r3) : "r"(addr));
}
__device__ __forceinline__ void mma_bf16(float* c, const unsigned* a, unsigned b0, unsigned b1) {
    asm volatile(
        "mma.sync.aligned.m16n8k16.row.col.f32.bf16.bf16.f32 "
        "{%0,%1,%2,%3},{%4,%5,%6,%7},{%8,%9},{%0,%1,%2,%3};"
        : "+f"(c[0]), "+f"(c[1]), "+f"(c[2]), "+f"(c[3])
        : "r"(a[0]), "r"(a[1]), "r"(a[2]), "r"(a[3]), "r"(b0), "r"(b1));
}

// ---------------- x transpose + hi/lo split ----------------
__global__ void __launch_bounds__(256) transpose_x(const float* __restrict__ x)
{
    size_t idx = (size_t)blockIdx.x * blockDim.x + threadIdx.x; // over P*B*T*32 float4
    if (idx >= (size_t)P_ * B_ * T_ * 32) return;
    int f4 = (int)(idx & 31);
    size_t r = idx >> 5;
    int t = (int)(r % T_);
    size_t r2 = r / T_;
    int b = (int)(r2 % B_);
    int p = (int)(r2 / B_);
    float4 v = ((const float4*)x)[idx];
    float vv[4] = {v.x, v.y, v.z, v.w};
    bf16 hi[4], lo[4];
#pragma unroll
    for (int i = 0; i < 4; i++) {
        hi[i] = __float2bfloat16(vv[i]);
        lo[i] = __float2bfloat16(vv[i] - __bfloat162float(hi[i]));
    }
    size_t off = ((size_t)(t * B_ + b) * 128 + p * 32 + f4) * 2; // in bf162 units
    ((__nv_bfloat162*)d_XtH)[off]     = __nv_bfloat162(hi[0], hi[1]);
    ((__nv_bfloat162*)d_XtH)[off + 1] = __nv_bfloat162(hi[2], hi[3]);
    ((__nv_bfloat162*)d_XtL)[off]     = __nv_bfloat162(lo[0], lo[1]);
    ((__nv_bfloat162*)d_XtL)[off + 1] = __nv_bfloat162(lo[2], lo[3]);
}

// ---------------- weight conversion ----------------
__global__ void convert_wg(const float* __restrict__ Wh, const float* __restrict__ Wx,
                           bf16* __restrict__ Hd, bf16* __restrict__ Ld)
{
    size_t idx = (size_t)blockIdx.x * blockDim.x + threadIdx.x;
    if (idx >= (size_t)P_ * KG * G3H) return;
    int c = (int)(idx % G3H);
    size_t r0 = idx / G3H;
    int k = (int)(r0 % KG);
    int p = (int)(r0 / KG);
    float v = (k < H_) ? Wh[((size_t)p * H_ + k) * G3H + c]
                       : Wx[((size_t)p * FP_ + (k - H_)) * G3H + c];
    bf16 h = __float2bfloat16(v);
    Hd[idx] = h;
    Ld[idx] = __float2bfloat16(v - __bfloat162float(h));
}
__global__ void convert_wo(const float* __restrict__ Who, const float* __restrict__ Wxo,
                           bf16* __restrict__ Hd, bf16* __restrict__ Ld)
{
    int idx = blockIdx.x * blockDim.x + threadIdx.x;
    if (idx >= KO * H_) return;
    int k = idx / H_, c = idx - k * H_;
    float v = (k < H_) ? Who[(size_t)k * H_ + c] : Wxo[(size_t)(k - H_) * H_ + c];
    bf16 h = __float2bfloat16(v);
    Hd[idx] = h;
    Ld[idx] = __float2bfloat16(v - __bfloat162float(h));
}

// ---------------- persistent recurrent kernel (split-bf16 tensor-core GEMM) ----------------
__global__ void __launch_bounds__(256, 2) recurrent_kernel(int nblk)
{
    __shared__ __align__(16) bf16 AsH[TM * KC];
    __shared__ __align__(16) bf16 AsL[TM * KC];
    __shared__ __align__(16) bf16 BsH[KC * TN];
    __shared__ __align__(16) bf16 BsL[KC * TN];

    const int tid  = threadIdx.x;
    const int lane = tid & 31;
    const int wid  = tid >> 5;
    const int warp_m = (wid >> 1) * 32;   // 0,32,64,96
    const int warp_n = (wid & 1) * 32;    // 0,32

    const unsigned asH = (unsigned)__cvta_generic_to_shared(AsH);
    const unsigned asL = (unsigned)__cvta_generic_to_shared(AsL);
    const unsigned bsH = (unsigned)__cvta_generic_to_shared(BsH);
    const unsigned bsL = (unsigned)__cvta_generic_to_shared(BsL);

    // ldmatrix lane offsets (bf16 elements), swizzled
    int offA[2][2], offB[2][2];
#pragma unroll
    for (int mf = 0; mf < 2; mf++)
#pragma unroll
        for (int kk = 0; kk < 2; kk++) {
            int r = warp_m + mf * 16 + (lane & 15);
            int g = (lane >> 4) + kk * 2;
            g ^= ((r >> 1) & 3);
            offA[mf][kk] = r * KC + g * 8;
        }
#pragma unroll
    for (int nf16 = 0; nf16 < 2; nf16++)
#pragma unroll
        for (int kk = 0; kk < 2; kk++) {
            int r = (lane & 15) + kk * 16;
            int g = (warp_n >> 3) + nf16 * 2 + (lane >> 4);
            g ^= (r & 7);
            offB[nf16][kk] = r * TN + g * 8;
        }

    // global->smem assignments
    int arI[2], agI[2], stA[2];
#pragma unroll
    for (int i = 0; i < 2; i++) {
        int idx = tid + i * 256;
        arI[i] = idx >> 2;
        agI[i] = idx & 3;
        stA[i] = arI[i] * KC + (agI[i] ^ ((arI[i] >> 1) & 3)) * 8;
    }
    const int br = tid >> 3, bg = tid & 7;
    const int stB = br * TN + (bg ^ (br & 7)) * 8;

    unsigned epoch = 0;

#pragma unroll 1
    for (int t = 0; t < T_; t++) {
#pragma unroll 1
        for (int l = 0; l < 2; l++) {
            const bf16* __restrict__ WgHp = d_WgH[l];
            const bf16* __restrict__ WgLp = d_WgL[l];
            const bf16* __restrict__ WoHp = d_WoH[l];
            const bf16* __restrict__ WoLp = d_WoL[l];
            const float* __restrict__ bias = d_bias[l];

#pragma unroll 1
            for (int tile = blockIdx.x; tile < NTILES; tile += nblk) {
                const int m0 = (tile / NTILE_N) * TM;
                const int j0 = (tile % NTILE_N) * TN;
                const bool isGate = (j0 < NG);
                const int p   = isGate ? (j0 / G3H) : 0;
                const int jc0 = isGate ? (j0 - p * G3H) : (j0 - NG);
                const bf16* WmH = isGate ? (WgHp + (size_t)p * KG * G3H + jc0) : (WoHp + jc0);
                const bf16* WmL = isGate ? (WgLp + (size_t)p * KG * G3H + jc0) : (WoLp + jc0);
                const int ldw  = isGate ? G3H : H_;
                const int NC   = (isGate ? KG : KO) / KC;
                const int xoff = isGate ? p * FP_ : 0;

                float acc[2][4][4];
#pragma unroll
                for (int a = 0; a < 2; a++)
#pragma unroll
                    for (int b = 0; b < 4; b++)
#pragma unroll
                        for (int c = 0; c < 4; c++) acc[a][b][c] = 0.0f;

                uint4 pAH[2], pAL[2], pBH, pBL;
                // ---- preload chunk 0
                {
                    const int kb = 0;
#pragma unroll
                    for (int i = 0; i < 2; i++) {
                        int bb = m0 + arI[i];
                        int kglob = kb + agI[i] * 8;
                        pAH[i] = __ldcg((const uint4*)&d_hbH[bb * H_ + kglob]);
                        pAL[i] = __ldcg((const uint4*)&d_hbL[bb * H_ + kglob]);
                    }
                    pBH = *(const uint4*)&WmH[(size_t)(kb + br) * ldw + bg * 8];
                    pBL = *(const uint4*)&WmL[(size_t)(kb + br) * ldw + bg * 8];
                }

#pragma unroll 1
                for (int ch = 0; ch < NC; ch++) {
                    __syncthreads();
#pragma unroll
                    for (int i = 0; i < 2; i++) {
                        *(uint4*)&AsH[stA[i]] = pAH[i];
                        *(uint4*)&AsL[stA[i]] = pAL[i];
                    }
                    *(uint4*)&BsH[stB] = pBH;
                    *(uint4*)&BsL[stB] = pBL;
                    __syncthreads();

                    // ---- prefetch next chunk
                    if (ch + 1 < NC) {
                        const int kb = (ch + 1) * KC;
                        const bool inH = kb < H_;
#pragma unroll
                        for (int i = 0; i < 2; i++) {
                            int bb = m0 + arI[i];
                            int kglob = kb + agI[i] * 8;
                            if (inH) {
                                pAH[i] = __ldcg((const uint4*)&d_hbH[bb * H_ + kglob]);
                                pAL[i] = __ldcg((const uint4*)&d_hbL[bb * H_ + kglob]);
                            } else {
                                size_t xo = ((size_t)(t * B_ + bb)) * 512 + xoff + (kglob - H_);
                                pAH[i] = *(const uint4*)&d_XtH[xo];
                                pAL[i] = *(const uint4*)&d_XtL[xo];
                            }
                        }
                        pBH = *(const uint4*)&WmH[(size_t)(kb + br) * ldw + bg * 8];
                        pBL = *(const uint4*)&WmL[(size_t)(kb + br) * ldw + bg * 8];
                    }

                    // ---- compute chunk
#pragma unroll
                    for (int kk = 0; kk < 2; kk++) {
                        unsigned aH[2][4], aL[2][4], bH[2][4], bL[2][4];
#pragma unroll
                        for (int mf = 0; mf < 2; mf++) {
                            ldsm4(aH[mf][0], aH[mf][1], aH[mf][2], aH[mf][3],
                                  asH + offA[mf][kk] * 2);
                            ldsm4(aL[mf][0], aL[mf][1], aL[mf][2], aL[mf][3],
                                  asL + offA[mf][kk] * 2);
                        }
#pragma unroll
                        for (int g = 0; g < 2; g++) {
                            ldsm4t(bH[g][0], bH[g][1], bH[g][2], bH[g][3],
                                   bsH + offB[g][kk] * 2);
                            ldsm4t(bL[g][0], bL[g][1], bL[g][2], bL[g][3],
                                   bsL + offB[g][kk] * 2);
                        }
#pragma unroll
                        for (int mf = 0; mf < 2; mf++)
#pragma unroll
                            for (int nf = 0; nf < 4; nf++) {
                                unsigned h0 = bH[nf >> 1][(nf & 1) * 2];
                                unsigned h1 = bH[nf >> 1][(nf & 1) * 2 + 1];
                                unsigned l0 = bL[nf >> 1][(nf & 1) * 2];
                                unsigned l1 = bL[nf >> 1][(nf & 1) * 2 + 1];
                                mma_bf16(acc[mf][nf], aH[mf], h0, h1);
                                mma_bf16(acc[mf][nf], aL[mf], h0, h1);
                                mma_bf16(acc[mf][nf], aH[mf], l0, l1);
                            }
                    }
                }

                // ---- epilogue: Z = acc + bias
#pragma unroll
                for (int mf = 0; mf < 2; mf++)
#pragma unroll
                    for (int nf = 0; nf < 4; nf++) {
                        int r0 = m0 + warp_m + mf * 16 + (lane >> 2);
                        int col = j0 + warp_n + nf * 8 + (lane & 3) * 2;
                        float2 bv = *(const float2*)&bias[col];
                        float2 z0 = make_float2(acc[mf][nf][0] + bv.x, acc[mf][nf][1] + bv.y);
                        float2 z1 = make_float2(acc[mf][nf][2] + bv.x, acc[mf][nf][3] + bv.y);
                        *(float2*)&d_Z[(size_t)r0 * NJ + col] = z0;
                        *(float2*)&d_Z[(size_t)(r0 + 8) * NJ + col] = z1;
                    }
            }
            epoch++; gridsync(epoch * (unsigned)nblk);

            // ---- elementwise LSTM update
            for (int idx = blockIdx.x * 256 + tid; idx < B_ * H_; idx += nblk * 256) {
                const int b = idx >> 9, hh = idx & (H_ - 1);
                const float* zr = d_Z + (size_t)b * NJ;
                float s = 0.0f;
#pragma unroll
                for (int p = 0; p < 4; p++) {
                    const int gb = p * G3H + hh;
                    float zi = __ldcg(zr + gb);
                    float zf = __ldcg(zr + gb + H_);
                    float zg = __ldcg(zr + gb + 2 * H_);
                    const int ci = ((b << 2) + p) * H_ + hh;
                    float cold = __ldcg(&d_cstate[ci]);
                    float cn = sigf(zf) * cold + sigf(zi) * tanhf(zg);
                    d_cstate[ci] = cn;
                    s += cn;
                }
                float o = sigf(__ldcg(zr + NG + hh));
                float hv = o * tanhf(s);
                d_hstate[idx] = hv;
                bf16 hi = __float2bfloat16(hv);
                d_hbH[idx] = hi;
                d_hbL[idx] = __float2bfloat16(hv - __bfloat162float(hi));
            }
            epoch++; gridsync(epoch * (unsigned)nblk);
        }
    }
}

// ---------------- classifier + log_softmax ----------------
__global__ void classifier(const float* __restrict__ Wfc, const float* __restrict__ bfc,
                           float* __restrict__ out)
{
    const int b = blockIdx.x;
    const int c = threadIdx.x;   // 64 threads
    __shared__ float sh[64];
    __shared__ float hrow[H_];
    for (int k = c; k < H_; k += 64) hrow[k] = d_hstate[b * H_ + k];
    __syncthreads();

    float z = -1e30f;
    if (c < C_) {
        z = bfc[c];
        for (int k = 0; k < H_; k++) z += hrow[k] * Wfc[k * C_ + c];
    }
    sh[c] = z; __syncthreads();
    for (int s = 32; s > 0; s >>= 1) {
        if (c < s) sh[c] = fmaxf(sh[c], sh[c + s]);
        __syncthreads();
    }
    const float mx = sh[0]; __syncthreads();
    float e = (c < C_) ? expf(z - mx) : 0.0f;
    sh[c] = e; __syncthreads();
    for (int s = 32; s > 0; s >>= 1) {
        if (c < s) sh[c] += sh[c + s];
        __syncthreads();
    }
    const float lse = logf(sh[0]) + mx;
    if (c < C_) out[b * C_ + c] = z - lse;
}

// ---------------- launch ----------------
extern "C" void kernel_launch(void* const* d_in, const int* in_sizes, int n_in,
                              void* d_out, int out_size)
{
    const float* x    = (const float*)d_in[0];
    const float* Wx1  = (const float*)d_in[1];
    const float* Wh1  = (const float*)d_in[2];
    const float* b1   = (const float*)d_in[3];
    const float* Wxo1 = (const float*)d_in[4];
    const float* Who1 = (const float*)d_in[5];
    const float* bo1  = (const float*)d_in[6];
    const float* Wx2  = (const float*)d_in[7];
    const float* Wh2  = (const float*)d_in[8];
    const float* b2   = (const float*)d_in[9];
    const float* Wxo2 = (const float*)d_in[10];
    const float* Who2 = (const float*)d_in[11];
    const float* bo2  = (const float*)d_in[12];
    const float* Wfc  = (const float*)d_in[13];
    const float* bfc  = (const float*)d_in[14];
    float* out = (float*)d_out;

    void *ph, *phbH, *phbL, *pc, *pg, *pb, *pwgH, *pwgL, *pwoH, *pwoL;
    cudaGetSymbolAddress(&ph, d_hstate);
    cudaGetSymbolAddress(&phbH, d_hbH);
    cudaGetSymbolAddress(&phbL, d_hbL);
    cudaGetSymbolAddress(&pc, d_cstate);
    cudaGetSymbolAddress(&pg, d_gcnt);
    cudaGetSymbolAddress(&pb, d_bias);
    cudaGetSymbolAddress(&pwgH, d_WgH);
    cudaGetSymbolAddress(&pwgL, d_WgL);
    cudaGetSymbolAddress(&pwoH, d_WoH);
    cudaGetSymbolAddress(&pwoL, d_WoL);

    cudaMemsetAsync(ph, 0, sizeof(float) * B_ * H_);
    cudaMemsetAsync(phbH, 0, sizeof(bf16) * B_ * H_);
    cudaMemsetAsync(phbL, 0, sizeof(bf16) * B_ * H_);
    cudaMemsetAsync(pc, 0, sizeof(float) * B_ * P_ * H_);
    cudaMemsetAsync(pg, 0, sizeof(unsigned));

    // biases (fp32 concat)
    cudaMemcpyAsync((float*)pb, b1, sizeof(float) * NG, cudaMemcpyDeviceToDevice);
    cudaMemcpyAsync((float*)pb + NG, bo1, sizeof(float) * H_, cudaMemcpyDeviceToDevice);
    cudaMemcpyAsync((float*)pb + NJ, b2, sizeof(float) * NG, cudaMemcpyDeviceToDevice);
    cudaMemcpyAsync((float*)pb + NJ + NG, bo2, sizeof(float) * H_, cudaMemcpyDeviceToDevice);

    // weight conversion to hi/lo bf16
    {
        size_t ng = (size_t)P_ * KG * G3H;
        unsigned gb = (unsigned)((ng + 255) / 256);
        convert_wg<<<gb, 256>>>(Wh1, Wx1, (bf16*)pwgH, (bf16*)pwgL);
        convert_wg<<<gb, 256>>>(Wh2, Wx2, (bf16*)pwgH + ng, (bf16*)pwgL + ng);
        unsigned ob = (KO * H_ + 255) / 256;
        convert_wo<<<ob, 256>>>(Who1, Wxo1, (bf16*)pwoH, (bf16*)pwoL);
        convert_wo<<<ob, 256>>>(Who2, Wxo2, (bf16*)pwoH + KO * H_, (bf16*)pwoL + KO * H_);
    }

    {
        size_t nf4 = (size_t)P_ * B_ * T_ * 32;
        transpose_x<<<(unsigned)((nf4 + 255) / 256), 256>>>(x);
    }

    int sms = 0, occ = 0;
    if (cudaDeviceGetAttribute(&sms, cudaDevAttrMultiProcessorCount, 0) != cudaSuccess
        || sms <= 0) sms = 148;
    if (cudaOccupancyMaxActiveBlocksPerMultiprocessor(&occ, recurrent_kernel, 256, 0)
        != cudaSuccess || occ <= 0) occ = 1;
    int nblk = sms * occ;
    if (nblk > NTILES) nblk = NTILES;
    recurrent_kernel<<<nblk, 256>>>(nblk);

    classifier<<<B_, 64>>>(Wfc, bfc, out);
}

// round 6
// speedup vs baseline: 2.8215x; 1.4920x over previous
#include <cuda_runtime.h>
#include <cuda_fp16.h>
#include <math.h>

// Problem constants
#define P_  4
#define FP_ 128
#define H_  512
#define C_  60
#define B_  256
#define T_  256
#define G3H 1536           // 3*H
#define NG  6144           // P*3H (gate cols)
#define NJ  6656           // gate cols + output-gate cols
#define KG  640            // K for gate tiles  (512 h + 128 x_p)
#define KO  1024           // K for output tiles (512 h + 512 x_flat)
#define TM  64             // CTA tile M
#define TN  64             // CTA tile N
#define KC  32             // k-chunk
#define NTILES 416         // (256/64) * (6656/64)
#define NTILE_N 104
#define NPHASE (2 * T_)    // 512 GEMM phases

typedef __half fp16;

// ---------------- device globals (~115 MB total) ----------------
__device__ fp16  d_Xt[(size_t)T_ * B_ * 512];     // x transposed fp16 (67 MB)
__device__ fp16  d_WgH[2][(size_t)P_ * KG * G3H]; // per layer/part: [Wh_p ; Wx_p] hi
__device__ fp16  d_WgL[2][(size_t)P_ * KG * G3H]; // lo
__device__ fp16  d_WoH[2][KO * H_];               // [Who ; Wxo] hi
__device__ fp16  d_WoL[2][KO * H_];
__device__ float d_bias[2][NJ];
__device__ float d_Z[(size_t)B_ * NJ];
__device__ float d_hstate[B_ * H_];
__device__ fp16  d_hb[B_ * H_];
__device__ float d_cstate[B_ * P_ * H_];
__device__ unsigned d_gcnt;
__device__ unsigned d_tcnt[NPHASE];               // per-phase dynamic tile counters

__device__ __forceinline__ float sigf(float x) { return 1.0f / (1.0f + expf(-x)); }

__device__ __forceinline__ void gridsync(unsigned target) {
    __threadfence();
    __syncthreads();
    if (threadIdx.x == 0) {
        atomicAdd(&d_gcnt, 1u);
        volatile unsigned* c = &d_gcnt;
        while (*c < target) { __nanosleep(32); }
    }
    __syncthreads();
}

__device__ __forceinline__ void ldsm4(unsigned& r0, unsigned& r1, unsigned& r2, unsigned& r3,
                                      unsigned addr) {
    asm volatile("ldmatrix.sync.aligned.m8n8.x4.shared.b16 {%0,%1,%2,%3},[%4];"
                 : "=r"(r0), "=r"(r1), "=r"(r2), "=r"(r3) : "r"(addr));
}
__device__ __forceinline__ void ldsm4t(unsigned& r0, unsigned& r1, unsigned& r2, unsigned& r3,
                                       unsigned addr) {
    asm volatile("ldmatrix.sync.aligned.m8n8.x4.trans.shared.b16 {%0,%1,%2,%3},[%4];"
                 : "=r"(r0), "=r"(r1), "=r"(r2), "=r"(r3) : "r"(addr));
}
__device__ __forceinline__ void mma_fp16(float* c, const unsigned* a, unsigned b0, unsigned b1) {
    asm volatile(
        "mma.sync.aligned.m16n8k16.row.col.f32.f16.f16.f32 "
        "{%0,%1,%2,%3},{%4,%5,%6,%7},{%8,%9},{%0,%1,%2,%3};"
        : "+f"(c[0]), "+f"(c[1]), "+f"(c[2]), "+f"(c[3])
        : "r"(a[0]), "r"(a[1]), "r"(a[2]), "r"(a[3]), "r"(b0), "r"(b1));
}

// ---------------- x transpose to fp16 ----------------
__global__ void __launch_bounds__(256) transpose_x(const float* __restrict__ x)
{
    size_t idx = (size_t)blockIdx.x * blockDim.x + threadIdx.x; // over P*B*T*32 float4
    if (idx >= (size_t)P_ * B_ * T_ * 32) return;
    int f4 = (int)(idx & 31);
    size_t r = idx >> 5;
    int t = (int)(r % T_);
    size_t r2 = r / T_;
    int b = (int)(r2 % B_);
    int p = (int)(r2 / B_);
    float4 v = ((const float4*)x)[idx];
    __half2 h0 = __floats2half2_rn(v.x, v.y);
    __half2 h1 = __floats2half2_rn(v.z, v.w);
    size_t off = ((size_t)(t * B_ + b) * 128 + p * 32 + f4) * 2; // half2 units
    ((__half2*)d_Xt)[off]     = h0;
    ((__half2*)d_Xt)[off + 1] = h1;
}

// ---------------- weight conversion (fp16 hi/lo) ----------------
__global__ void convert_wg(const float* __restrict__ Wh, const float* __restrict__ Wx,
                           fp16* __restrict__ Hd, fp16* __restrict__ Ld)
{
    size_t idx = (size_t)blockIdx.x * blockDim.x + threadIdx.x;
    if (idx >= (size_t)P_ * KG * G3H) return;
    int c = (int)(idx % G3H);
    size_t r0 = idx / G3H;
    int k = (int)(r0 % KG);
    int p = (int)(r0 / KG);
    float v = (k < H_) ? Wh[((size_t)p * H_ + k) * G3H + c]
                       : Wx[((size_t)p * FP_ + (k - H_)) * G3H + c];
    fp16 h = __float2half_rn(v);
    Hd[idx] = h;
    Ld[idx] = __float2half_rn(v - __half2float(h));
}
__global__ void convert_wo(const float* __restrict__ Who, const float* __restrict__ Wxo,
                           fp16* __restrict__ Hd, fp16* __restrict__ Ld)
{
    int idx = blockIdx.x * blockDim.x + threadIdx.x;
    if (idx >= KO * H_) return;
    int k = idx / H_, c = idx - k * H_;
    float v = (k < H_) ? Who[(size_t)k * H_ + c] : Wxo[(size_t)(k - H_) * H_ + c];
    fp16 h = __float2half_rn(v);
    Hd[idx] = h;
    Ld[idx] = __float2half_rn(v - __half2float(h));
}

// ---------------- persistent recurrent kernel (fp16 2-pass tensor-core GEMM) ----------------
__global__ void __launch_bounds__(128, 4) recurrent_kernel(int nblk)
{
    __shared__ __align__(16) fp16 As[TM * KC];     // 4 KB
    __shared__ __align__(16) fp16 BsH[KC * TN];    // 4 KB
    __shared__ __align__(16) fp16 BsL[KC * TN];    // 4 KB

    const int tid  = threadIdx.x;
    const int lane = tid & 31;
    const int wid  = tid >> 5;                     // 0..3
    const int warp_m = (wid & 1) * 32;             // 0,32
    const int warp_n = (wid >> 1) * 32;            // 0,32

    const unsigned asA = (unsigned)__cvta_generic_to_shared(As);
    const unsigned bsH = (unsigned)__cvta_generic_to_shared(BsH);
    const unsigned bsL = (unsigned)__cvta_generic_to_shared(BsL);

    // ldmatrix lane offsets (fp16 elements), swizzled
    int offA[2][2], offB[2][2];
#pragma unroll
    for (int mf = 0; mf < 2; mf++)
#pragma unroll
        for (int kk = 0; kk < 2; kk++) {
            int r = warp_m + mf * 16 + (lane & 15);
            int g = (lane >> 4) + kk * 2;
            g ^= ((r >> 1) & 3);
            offA[mf][kk] = r * KC + g * 8;
        }
#pragma unroll
    for (int nf16 = 0; nf16 < 2; nf16++)
#pragma unroll
        for (int kk = 0; kk < 2; kk++) {
            int r = (lane & 15) + kk * 16;
            int g = (warp_n >> 3) + nf16 * 2 + (lane >> 4);
            g ^= (r & 7);
            offB[nf16][kk] = r * TN + g * 8;
        }

    // global->smem assignments: A 256 slots (64r x 4g), B 256 slots (32r x 8g); 2 each
    int arI[2], agI[2], stA[2], brI[2], bgI[2], stB[2];
#pragma unroll
    for (int i = 0; i < 2; i++) {
        int idx = tid + i * 128;
        arI[i] = idx >> 2;
        agI[i] = idx & 3;
        stA[i] = arI[i] * KC + (agI[i] ^ ((arI[i] >> 1) & 3)) * 8;
        brI[i] = idx >> 3;
        bgI[i] = idx & 7;
        stB[i] = brI[i] * TN + (bgI[i] ^ (brI[i] & 7)) * 8;
    }

    unsigned epoch = 0;

#pragma unroll 1
    for (int t = 0; t < T_; t++) {
#pragma unroll 1
        for (int l = 0; l < 2; l++) {
            const fp16* __restrict__ WgHp = d_WgH[l];
            const fp16* __restrict__ WgLp = d_WgL[l];
            const fp16* __restrict__ WoHp = d_WoH[l];
            const fp16* __restrict__ WoLp = d_WoL[l];
            const float* __restrict__ bias = d_bias[l];
            unsigned* __restrict__ tc = &d_tcnt[t * 2 + l];

#pragma unroll 1
            for (;;) {
                unsigned tile;
                if (tid == 0) tile = atomicAdd(tc, 1u);
                tile = __shfl_sync(0xffffffff, tile, 0);
                __shared__ unsigned s_tile;
                if (tid == 0) s_tile = tile;
                __syncthreads();
                tile = s_tile;
                if (tile >= NTILES) break;

                const int m0 = ((int)tile / NTILE_N) * TM;
                const int j0 = ((int)tile % NTILE_N) * TN;
                const bool isGate = (j0 < NG);
                const int p   = isGate ? (j0 / G3H) : 0;
                const int jc0 = isGate ? (j0 - p * G3H) : (j0 - NG);
                const fp16* WmH = isGate ? (WgHp + (size_t)p * KG * G3H + jc0) : (WoHp + jc0);
                const fp16* WmL = isGate ? (WgLp + (size_t)p * KG * G3H + jc0) : (WoLp + jc0);
                const int ldw  = isGate ? G3H : H_;
                const int NC   = (isGate ? KG : KO) / KC;
                const int xoff = isGate ? p * FP_ : 0;

                float acc[2][4][4];
#pragma unroll
                for (int a = 0; a < 2; a++)
#pragma unroll
                    for (int b = 0; b < 4; b++)
#pragma unroll
                        for (int c = 0; c < 4; c++) acc[a][b][c] = 0.0f;

                uint4 pA[2], pBH[2], pBL[2];
                // ---- preload chunk 0 (k < H always)
#pragma unroll
                for (int i = 0; i < 2; i++) {
                    int bb = m0 + arI[i];
                    int kglob = agI[i] * 8;
                    pA[i] = __ldcg((const uint4*)&d_hb[bb * H_ + kglob]);
                    pBH[i] = *(const uint4*)&WmH[(size_t)brI[i] * ldw + bgI[i] * 8];
                    pBL[i] = *(const uint4*)&WmL[(size_t)brI[i] * ldw + bgI[i] * 8];
                }

#pragma unroll 1
                for (int ch = 0; ch < NC; ch++) {
                    __syncthreads();
#pragma unroll
                    for (int i = 0; i < 2; i++) {
                        *(uint4*)&As[stA[i]] = pA[i];
                        *(uint4*)&BsH[stB[i]] = pBH[i];
                        *(uint4*)&BsL[stB[i]] = pBL[i];
                    }
                    __syncthreads();

                    // ---- prefetch next chunk
                    if (ch + 1 < NC) {
                        const int kb = (ch + 1) * KC;
                        const bool inH = kb < H_;
#pragma unroll
                        for (int i = 0; i < 2; i++) {
                            int bb = m0 + arI[i];
                            int kglob = kb + agI[i] * 8;
                            if (inH) {
                                pA[i] = __ldcg((const uint4*)&d_hb[bb * H_ + kglob]);
                            } else {
                                size_t xo = ((size_t)(t * B_ + bb)) * 512 + xoff + (kglob - H_);
                                pA[i] = *(const uint4*)&d_Xt[xo];
                            }
                            pBH[i] = *(const uint4*)&WmH[(size_t)(kb + brI[i]) * ldw + bgI[i] * 8];
                            pBL[i] = *(const uint4*)&WmL[(size_t)(kb + brI[i]) * ldw + bgI[i] * 8];
                        }
                    }

                    // ---- compute chunk
#pragma unroll
                    for (int kk = 0; kk < 2; kk++) {
                        unsigned a[2][4], bH[2][4], bL[2][4];
#pragma unroll
                        for (int mf = 0; mf < 2; mf++)
                            ldsm4(a[mf][0], a[mf][1], a[mf][2], a[mf][3],
                                  asA + offA[mf][kk] * 2);
#pragma unroll
                        for (int g = 0; g < 2; g++) {
                            ldsm4t(bH[g][0], bH[g][1], bH[g][2], bH[g][3],
                                   bsH + offB[g][kk] * 2);
                            ldsm4t(bL[g][0], bL[g][1], bL[g][2], bL[g][3],
                                   bsL + offB[g][kk] * 2);
                        }
#pragma unroll
                        for (int mf = 0; mf < 2; mf++)
#pragma unroll
                            for (int nf = 0; nf < 4; nf++) {
                                unsigned h0 = bH[nf >> 1][(nf & 1) * 2];
                                unsigned h1 = bH[nf >> 1][(nf & 1) * 2 + 1];
                                unsigned l0 = bL[nf >> 1][(nf & 1) * 2];
                                unsigned l1 = bL[nf >> 1][(nf & 1) * 2 + 1];
                                mma_fp16(acc[mf][nf], a[mf], h0, h1);
                                mma_fp16(acc[mf][nf], a[mf], l0, l1);
                            }
                    }
                }

                // ---- epilogue: Z = acc + bias
#pragma unroll
                for (int mf = 0; mf < 2; mf++)
#pragma unroll
                    for (int nf = 0; nf < 4; nf++) {
                        int r0 = m0 + warp_m + mf * 16 + (lane >> 2);
                        int col = j0 + warp_n + nf * 8 + (lane & 3) * 2;
                        float2 bv = *(const float2*)&bias[col];
                        float2 z0 = make_float2(acc[mf][nf][0] + bv.x, acc[mf][nf][1] + bv.y);
                        float2 z1 = make_float2(acc[mf][nf][2] + bv.x, acc[mf][nf][3] + bv.y);
                        *(float2*)&d_Z[(size_t)r0 * NJ + col] = z0;
                        *(float2*)&d_Z[(size_t)(r0 + 8) * NJ + col] = z1;
                    }
            }
            epoch++; gridsync(epoch * (unsigned)nblk);

            // ---- elementwise LSTM update
            for (int idx = blockIdx.x * 128 + tid; idx < B_ * H_; idx += nblk * 128) {
                const int b = idx >> 9, hh = idx & (H_ - 1);
                const float* zr = d_Z + (size_t)b * NJ;
                float s = 0.0f;
#pragma unroll
                for (int p = 0; p < 4; p++) {
                    const int gb = p * G3H + hh;
                    float zi = __ldcg(zr + gb);
                    float zf = __ldcg(zr + gb + H_);
                    float zg = __ldcg(zr + gb + 2 * H_);
                    const int ci = ((b << 2) + p) * H_ + hh;
                    float cold = __ldcg(&d_cstate[ci]);
                    float cn = sigf(zf) * cold + sigf(zi) * tanhf(zg);
                    d_cstate[ci] = cn;
                    s += cn;
                }
                float o = sigf(__ldcg(zr + NG + hh));
                float hv = o * tanhf(s);
                d_hstate[idx] = hv;
                d_hb[idx] = __float2half_rn(hv);
            }
            epoch++; gridsync(epoch * (unsigned)nblk);
        }
    }
}

// ---------------- classifier + log_softmax ----------------
__global__ void classifier(const float* __restrict__ Wfc, const float* __restrict__ bfc,
                           float* __restrict__ out)
{
    const int b = blockIdx.x;
    const int c = threadIdx.x;   // 64 threads
    __shared__ float sh[64];
    __shared__ float hrow[H_];
    for (int k = c; k < H_; k += 64) hrow[k] = d_hstate[b * H_ + k];
    __syncthreads();

    float z = -1e30f;
    if (c < C_) {
        z = bfc[c];
        for (int k = 0; k < H_; k++) z += hrow[k] * Wfc[k * C_ + c];
    }
    sh[c] = z; __syncthreads();
    for (int s = 32; s > 0; s >>= 1) {
        if (c < s) sh[c] = fmaxf(sh[c], sh[c + s]);
        __syncthreads();
    }
    const float mx = sh[0]; __syncthreads();
    float e = (c < C_) ? expf(z - mx) : 0.0f;
    sh[c] = e; __syncthreads();
    for (int s = 32; s > 0; s >>= 1) {
        if (c < s) sh[c] += sh[c + s];
        __syncthreads();
    }
    const float lse = logf(sh[0]) + mx;
    if (c < C_) out[b * C_ + c] = z - lse;
}

// ---------------- launch ----------------
extern "C" void kernel_launch(void* const* d_in, const int* in_sizes, int n_in,
                              void* d_out, int out_size)
{
    const float* x    = (const float*)d_in[0];
    const float* Wx1  = (const float*)d_in[1];
    const float* Wh1  = (const float*)d_in[2];
    const float* b1   = (const float*)d_in[3];
    const float* Wxo1 = (const float*)d_in[4];
    const float* Who1 = (const float*)d_in[5];
    const float* bo1  = (const float*)d_in[6];
    const float* Wx2  = (const float*)d_in[7];
    const float* Wh2  = (const float*)d_in[8];
    const float* b2   = (const float*)d_in[9];
    const float* Wxo2 = (const float*)d_in[10];
    const float* Who2 = (const float*)d_in[11];
    const float* bo2  = (const float*)d_in[12];
    const float* Wfc  = (const float*)d_in[13];
    const float* bfc  = (const float*)d_in[14];
    float* out = (float*)d_out;

    void *ph, *phb, *pc, *pg, *ptc, *pb, *pwgH, *pwgL, *pwoH, *pwoL;
    cudaGetSymbolAddress(&ph, d_hstate);
    cudaGetSymbolAddress(&phb, d_hb);
    cudaGetSymbolAddress(&pc, d_cstate);
    cudaGetSymbolAddress(&pg, d_gcnt);
    cudaGetSymbolAddress(&ptc, d_tcnt);
    cudaGetSymbolAddress(&pb, d_bias);
    cudaGetSymbolAddress(&pwgH, d_WgH);
    cudaGetSymbolAddress(&pwgL, d_WgL);
    cudaGetSymbolAddress(&pwoH, d_WoH);
    cudaGetSymbolAddress(&pwoL, d_WoL);

    cudaMemsetAsync(ph, 0, sizeof(float) * B_ * H_);
    cudaMemsetAsync(phb, 0, sizeof(fp16) * B_ * H_);
    cudaMemsetAsync(pc, 0, sizeof(float) * B_ * P_ * H_);
    cudaMemsetAsync(pg, 0, sizeof(unsigned));
    cudaMemsetAsync(ptc, 0, sizeof(unsigned) * NPHASE);

    // biases (fp32 concat)
    cudaMemcpyAsync((float*)pb, b1, sizeof(float) * NG, cudaMemcpyDeviceToDevice);
    cudaMemcpyAsync((float*)pb + NG, bo1, sizeof(float) * H_, cudaMemcpyDeviceToDevice);
    cudaMemcpyAsync((float*)pb + NJ, b2, sizeof(float) * NG, cudaMemcpyDeviceToDevice);
    cudaMemcpyAsync((float*)pb + NJ + NG, bo2, sizeof(float) * H_, cudaMemcpyDeviceToDevice);

    // weight conversion to fp16 hi/lo
    {
        size_t ng = (size_t)P_ * KG * G3H;
        unsigned gb = (unsigned)((ng + 255) / 256);
        convert_wg<<<gb, 256>>>(Wh1, Wx1, (fp16*)pwgH, (fp16*)pwgL);
        convert_wg<<<gb, 256>>>(Wh2, Wx2, (fp16*)pwgH + ng, (fp16*)pwgL + ng);
        unsigned ob = (KO * H_ + 255) / 256;
        convert_wo<<<ob, 256>>>(Who1, Wxo1, (fp16*)pwoH, (fp16*)pwoL);
        convert_wo<<<ob, 256>>>(Who2, Wxo2, (fp16*)pwoH + KO * H_, (fp16*)pwoL + KO * H_);
    }

    {
        size_t nf4 = (size_t)P_ * B_ * T_ * 32;
        transpose_x<<<(unsigned)((nf4 + 255) / 256), 256>>>(x);
    }

    int sms = 0, occ = 0;
    if (cudaDeviceGetAttribute(&sms, cudaDevAttrMultiProcessorCount, 0) != cudaSuccess
        || sms <= 0) sms = 148;
    if (cudaOccupancyMaxActiveBlocksPerMultiprocessor(&occ, recurrent_kernel, 128, 0)
        != cudaSuccess || occ <= 0) occ = 2;
    int nblk = sms * occ;
    if (nblk > NTILES) nblk = NTILES;
    recurrent_kernel<<<nblk, 128>>>(nblk);

    classifier<<<B_, 64>>>(Wfc, bfc, out);
}

// round 8
// speedup vs baseline: 3.4999x; 1.2405x over previous
#include <cuda_runtime.h>
#include <cuda_fp16.h>
#include <math.h>

// Problem constants
#define P_  4
#define FP_ 128
#define H_  512
#define C_  60
#define B_  256
#define T_  256
#define G3H 1536           // 3*H
#define NG  6144           // P*3H (gate cols)
#define NJ  6656           // gate cols + output-gate cols
#define KG  640            // K for gate tiles  (512 h + 128 x_p)
#define KO  1024           // K for output tiles (512 h + 512 x_flat)
#define TM  64             // CTA tile M
#define TN  64             // CTA tile N
#define KC  32             // k-chunk
#define NTILES 416         // (256/64) * (6656/64)
#define NTILE_N 104
#define NPHASE (2 * T_)    // 512 GEMM phases

typedef __half fp16;

// ---------------- device globals (~90 MB total) ----------------
__device__ fp16  d_Xt[(size_t)T_ * B_ * 512];     // x transposed fp16 (67 MB)
__device__ fp16  d_Wg[2][(size_t)P_ * KG * G3H];  // per layer/part: [Wh_p ; Wx_p]
__device__ fp16  d_Wo[2][KO * H_];                // [Who ; Wxo]
__device__ float d_bias[2][NJ];
__device__ float d_Z[(size_t)B_ * NJ];
__device__ float d_hstate[B_ * H_];
__device__ fp16  d_hb[B_ * H_];
__device__ float d_cstate[B_ * P_ * H_];
__device__ unsigned d_gcnt;
__device__ unsigned d_tcnt[NPHASE];               // per-phase dynamic tile counters

__device__ __forceinline__ float sigf(float x) { return 1.0f / (1.0f + expf(-x)); }

__device__ __forceinline__ void gridsync(unsigned target) {
    __threadfence();
    __syncthreads();
    if (threadIdx.x == 0) {
        atomicAdd(&d_gcnt, 1u);
        volatile unsigned* c = &d_gcnt;
        while (*c < target) { __nanosleep(32); }
    }
    __syncthreads();
}

__device__ __forceinline__ void ldsm4(unsigned& r0, unsigned& r1, unsigned& r2, unsigned& r3,
                                      unsigned addr) {
    asm volatile("ldmatrix.sync.aligned.m8n8.x4.shared.b16 {%0,%1,%2,%3},[%4];"
                 : "=r"(r0), "=r"(r1), "=r"(r2), "=r"(r3) : "r"(addr));
}
__device__ __forceinline__ void ldsm4t(unsigned& r0, unsigned& r1, unsigned& r2, unsigned& r3,
                                       unsigned addr) {
    asm volatile("ldmatrix.sync.aligned.m8n8.x4.trans.shared.b16 {%0,%1,%2,%3},[%4];"
                 : "=r"(r0), "=r"(r1), "=r"(r2), "=r"(r3) : "r"(addr));
}
__device__ __forceinline__ void mma_fp16(float* c, const unsigned* a, unsigned b0, unsigned b1) {
    asm volatile(
        "mma.sync.aligned.m16n8k16.row.col.f32.f16.f16.f32 "
        "{%0,%1,%2,%3},{%4,%5,%6,%7},{%8,%9},{%0,%1,%2,%3};"
        : "+f"(c[0]), "+f"(c[1]), "+f"(c[2]), "+f"(c[3])
        : "r"(a[0]), "r"(a[1]), "r"(a[2]), "r"(a[3]), "r"(b0), "r"(b1));
}

// ---------------- x transpose to fp16 ----------------
__global__ void __launch_bounds__(256) transpose_x(const float* __restrict__ x)
{
    size_t idx = (size_t)blockIdx.x * blockDim.x + threadIdx.x; // over P*B*T*32 float4
    if (idx >= (size_t)P_ * B_ * T_ * 32) return;
    int f4 = (int)(idx & 31);
    size_t r = idx >> 5;
    int t = (int)(r % T_);
    size_t r2 = r / T_;
    int b = (int)(r2 % B_);
    int p = (int)(r2 / B_);
    float4 v = ((const float4*)x)[idx];
    __half2 h0 = __floats2half2_rn(v.x, v.y);
    __half2 h1 = __floats2half2_rn(v.z, v.w);
    size_t off = ((size_t)(t * B_ + b) * 128 + p * 32 + f4) * 2; // half2 units
    ((__half2*)d_Xt)[off]     = h0;
    ((__half2*)d_Xt)[off + 1] = h1;
}

// ---------------- weight conversion (single fp16) ----------------
__global__ void convert_wg(const float* __restrict__ Wh, const float* __restrict__ Wx,
                           fp16* __restrict__ Wd)
{
    size_t idx = (size_t)blockIdx.x * blockDim.x + threadIdx.x;
    if (idx >= (size_t)P_ * KG * G3H) return;
    int c = (int)(idx % G3H);
    size_t r0 = idx / G3H;
    int k = (int)(r0 % KG);
    int p = (int)(r0 / KG);
    float v = (k < H_) ? Wh[((size_t)p * H_ + k) * G3H + c]
                       : Wx[((size_t)p * FP_ + (k - H_)) * G3H + c];
    Wd[idx] = __float2half_rn(v);
}
__global__ void convert_wo(const float* __restrict__ Who, const float* __restrict__ Wxo,
                           fp16* __restrict__ Wd)
{
    int idx = blockIdx.x * blockDim.x + threadIdx.x;
    if (idx >= KO * H_) return;
    int k = idx / H_, c = idx - k * H_;
    float v = (k < H_) ? Who[(size_t)k * H_ + c] : Wxo[(size_t)(k - H_) * H_ + c];
    Wd[idx] = __float2half_rn(v);
}

// ---------------- persistent recurrent kernel (fp16 single-pass, double-buffered) ----------------
__global__ void __launch_bounds__(128, 4) recurrent_kernel(int nblk)
{
    __shared__ __align__(16) fp16 As[2][TM * KC];  // 2 x 4 KB
    __shared__ __align__(16) fp16 Bs[2][KC * TN];  // 2 x 4 KB
    __shared__ unsigned s_tile;

    const int tid  = threadIdx.x;
    const int lane = tid & 31;
    const int wid  = tid >> 5;                     // 0..3
    const int warp_m = (wid & 1) * 32;             // 0,32
    const int warp_n = (wid >> 1) * 32;            // 0,32

    const unsigned asA = (unsigned)__cvta_generic_to_shared(&As[0][0]);
    const unsigned bsB = (unsigned)__cvta_generic_to_shared(&Bs[0][0]);

    // ldmatrix lane offsets (fp16 elements within one buffer), swizzled
    int offA[2][2], offB[2][2];
#pragma unroll
    for (int mf = 0; mf < 2; mf++)
#pragma unroll
        for (int kk = 0; kk < 2; kk++) {
            int r = warp_m + mf * 16 + (lane & 15);
            int g = (lane >> 4) + kk * 2;
            g ^= ((r >> 1) & 3);
            offA[mf][kk] = r * KC + g * 8;
        }
#pragma unroll
    for (int nf16 = 0; nf16 < 2; nf16++)
#pragma unroll
        for (int kk = 0; kk < 2; kk++) {
            int r = (lane & 15) + kk * 16;
            int g = (warp_n >> 3) + nf16 * 2 + (lane >> 4);
            g ^= (r & 7);
            offB[nf16][kk] = r * TN + g * 8;
        }

    // global->smem assignments: A 256 slots (64r x 4g), B 256 slots (32r x 8g); 2 each
    int arI[2], agI[2], stA[2], brI[2], bgI[2], stB[2];
#pragma unroll
    for (int i = 0; i < 2; i++) {
        int idx = tid + i * 128;
        arI[i] = idx >> 2;
        agI[i] = idx & 3;
        stA[i] = arI[i] * KC + (agI[i] ^ ((arI[i] >> 1) & 3)) * 8;
        brI[i] = idx >> 3;
        bgI[i] = idx & 7;
        stB[i] = brI[i] * TN + (bgI[i] ^ (brI[i] & 7)) * 8;
    }

    unsigned epoch = 0;

#pragma unroll 1
    for (int t = 0; t < T_; t++) {
#pragma unroll 1
        for (int l = 0; l < 2; l++) {
            const fp16* __restrict__ Wgp = d_Wg[l];
            const fp16* __restrict__ Wop = d_Wo[l];
            const float* __restrict__ bias = d_bias[l];
            unsigned* __restrict__ tc = &d_tcnt[t * 2 + l];

#pragma unroll 1
            for (;;) {
                if (tid == 0) s_tile = atomicAdd(tc, 1u);
                __syncthreads();
                const unsigned tile = s_tile;
                __syncthreads();
                if (tile >= NTILES) break;

                const int m0 = ((int)tile / NTILE_N) * TM;
                const int j0 = ((int)tile % NTILE_N) * TN;
                const bool isGate = (j0 < NG);
                const int p   = isGate ? (j0 / G3H) : 0;
                const int jc0 = isGate ? (j0 - p * G3H) : (j0 - NG);
                const fp16* Wm = isGate ? (Wgp + (size_t)p * KG * G3H + jc0) : (Wop + jc0);
                const int ldw  = isGate ? G3H : H_;
                const int NC   = (isGate ? KG : KO) / KC;
                const int xoff = isGate ? p * FP_ : 0;

                float acc[2][4][4];
#pragma unroll
                for (int a = 0; a < 2; a++)
#pragma unroll
                    for (int b = 0; b < 4; b++)
#pragma unroll
                        for (int c = 0; c < 4; c++) acc[a][b][c] = 0.0f;

                // ---- chunk 0 -> buffer 0 (k < H always)
#pragma unroll
                for (int i = 0; i < 2; i++) {
                    *(uint4*)&As[0][stA[i]] =
                        __ldcg((const uint4*)&d_hb[(m0 + arI[i]) * H_ + agI[i] * 8]);
                    *(uint4*)&Bs[0][stB[i]] =
                        *(const uint4*)&Wm[(size_t)brI[i] * ldw + bgI[i] * 8];
                }
                __syncthreads();

#pragma unroll 1
                for (int ch = 0; ch < NC; ch++) {
                    const int cur = ch & 1;

                    // ---- prefetch chunk ch+1 into regs (overlaps compute)
                    uint4 pA[2], pB[2];
                    const bool more = (ch + 1 < NC);   // block-uniform
                    if (more) {
                        const int kb = (ch + 1) * KC;
                        const bool inH = kb < H_;
#pragma unroll
                        for (int i = 0; i < 2; i++) {
                            int bb = m0 + arI[i];
                            int kglob = kb + agI[i] * 8;
                            if (inH) {
                                pA[i] = __ldcg((const uint4*)&d_hb[bb * H_ + kglob]);
                            } else {
                                size_t xo = ((size_t)(t * B_ + bb)) * 512 + xoff + (kglob - H_);
                                pA[i] = *(const uint4*)&d_Xt[xo];
                            }
                            pB[i] = *(const uint4*)&Wm[(size_t)(kb + brI[i]) * ldw + bgI[i] * 8];
                        }
                    }

                    // ---- compute current buffer
                    const unsigned aBase = asA + cur * (TM * KC * 2);
                    const unsigned bBase = bsB + cur * (KC * TN * 2);
#pragma unroll
                    for (int kk = 0; kk < 2; kk++) {
                        unsigned a[2][4], b[2][4];
#pragma unroll
                        for (int mf = 0; mf < 2; mf++)
                            ldsm4(a[mf][0], a[mf][1], a[mf][2], a[mf][3],
                                  aBase + offA[mf][kk] * 2);
#pragma unroll
                        for (int g = 0; g < 2; g++)
                            ldsm4t(b[g][0], b[g][1], b[g][2], b[g][3],
                                   bBase + offB[g][kk] * 2);
#pragma unroll
                        for (int mf = 0; mf < 2; mf++)
#pragma unroll
                            for (int nf = 0; nf < 4; nf++)
                                mma_fp16(acc[mf][nf], a[mf],
                                         b[nf >> 1][(nf & 1) * 2],
                                         b[nf >> 1][(nf & 1) * 2 + 1]);
                    }

                    // ---- store prefetched regs into the other buffer
                    if (more) {
                        const int nxt = cur ^ 1;
#pragma unroll
                        for (int i = 0; i < 2; i++) {
                            *(uint4*)&As[nxt][stA[i]] = pA[i];
                            *(uint4*)&Bs[nxt][stB[i]] = pB[i];
                        }
                        __syncthreads();
                    }
                }

                // ---- epilogue: Z = acc + bias
#pragma unroll
                for (int mf = 0; mf < 2; mf++)
#pragma unroll
                    for (int nf = 0; nf < 4; nf++) {
                        int r0 = m0 + warp_m + mf * 16 + (lane >> 2);
                        int col = j0 + warp_n + nf * 8 + (lane & 3) * 2;
                        float2 bv = *(const float2*)&bias[col];
                        float2 z0 = make_float2(acc[mf][nf][0] + bv.x, acc[mf][nf][1] + bv.y);
                        float2 z1 = make_float2(acc[mf][nf][2] + bv.x, acc[mf][nf][3] + bv.y);
                        *(float2*)&d_Z[(size_t)r0 * NJ + col] = z0;
                        *(float2*)&d_Z[(size_t)(r0 + 8) * NJ + col] = z1;
                    }
                __syncthreads();
            }
            epoch++; gridsync(epoch * (unsigned)nblk);

            // ---- elementwise LSTM update
            for (int idx = blockIdx.x * 128 + tid; idx < B_ * H_; idx += nblk * 128) {
                const int b = idx >> 9, hh = idx & (H_ - 1);
                const float* zr = d_Z + (size_t)b * NJ;
                float s = 0.0f;
#pragma unroll
                for (int p = 0; p < 4; p++) {
                    const int gb = p * G3H + hh;
                    float zi = __ldcg(zr + gb);
                    float zf = __ldcg(zr + gb + H_);
                    float zg = __ldcg(zr + gb + 2 * H_);
                    const int ci = ((b << 2) + p) * H_ + hh;
                    float cold = __ldcg(&d_cstate[ci]);
                    float cn = sigf(zf) * cold + sigf(zi) * tanhf(zg);
                    d_cstate[ci] = cn;
                    s += cn;
                }
                float o = sigf(__ldcg(zr + NG + hh));
                float hv = o * tanhf(s);
                d_hstate[idx] = hv;
                d_hb[idx] = __float2half_rn(hv);
            }
            epoch++; gridsync(epoch * (unsigned)nblk);
        }
    }
}

// ---------------- classifier + log_softmax ----------------
__global__ void classifier(const float* __restrict__ Wfc, const float* __restrict__ bfc,
                           float* __restrict__ out)
{
    const int b = blockIdx.x;
    const int c = threadIdx.x;   // 64 threads
    __shared__ float sh[64];
    __shared__ float hrow[H_];
    for (int k = c; k < H_; k += 64) hrow[k] = d_hstate[b * H_ + k];
    __syncthreads();

    float z = -1e30f;
    if (c < C_) {
        z = bfc[c];
        for (int k = 0; k < H_; k++) z += hrow[k] * Wfc[k * C_ + c];
    }
    sh[c] = z; __syncthreads();
    for (int s = 32; s > 0; s >>= 1) {
        if (c < s) sh[c] = fmaxf(sh[c], sh[c + s]);
        __syncthreads();
    }
    const float mx = sh[0]; __syncthreads();
    float e = (c < C_) ? expf(z - mx) : 0.0f;
    sh[c] = e; __syncthreads();
    for (int s = 32; s > 0; s >>= 1) {
        if (c < s) sh[c] += sh[c + s];
        __syncthreads();
    }
    const float lse = logf(sh[0]) + mx;
    if (c < C_) out[b * C_ + c] = z - lse;
}

// ---------------- launch ----------------
extern "C" void kernel_launch(void* const* d_in, const int* in_sizes, int n_in,
                              void* d_out, int out_size)
{
    const float* x    = (const float*)d_in[0];
    const float* Wx1  = (const float*)d_in[1];
    const float* Wh1  = (const float*)d_in[2];
    const float* b1   = (const float*)d_in[3];
    const float* Wxo1 = (const float*)d_in[4];
    const float* Who1 = (const float*)d_in[5];
    const float* bo1  = (const float*)d_in[6];
    const float* Wx2  = (const float*)d_in[7];
    const float* Wh2  = (const float*)d_in[8];
    const float* b2   = (const float*)d_in[9];
    const float* Wxo2 = (const float*)d_in[10];
    const float* Who2 = (const float*)d_in[11];
    const float* bo2  = (const float*)d_in[12];
    const float* Wfc  = (const float*)d_in[13];
    const float* bfc  = (const float*)d_in[14];
    float* out = (float*)d_out;

    void *ph, *phb, *pc, *pg, *ptc, *pb, *pwg, *pwo;
    cudaGetSymbolAddress(&ph, d_hstate);
    cudaGetSymbolAddress(&phb, d_hb);
    cudaGetSymbolAddress(&pc, d_cstate);
    cudaGetSymbolAddress(&pg, d_gcnt);
    cudaGetSymbolAddress(&ptc, d_tcnt);
    cudaGetSymbolAddress(&pb, d_bias);
    cudaGetSymbolAddress(&pwg, d_Wg);
    cudaGetSymbolAddress(&pwo, d_Wo);

    cudaMemsetAsync(ph, 0, sizeof(float) * B_ * H_);
    cudaMemsetAsync(phb, 0, sizeof(fp16) * B_ * H_);
    cudaMemsetAsync(pc, 0, sizeof(float) * B_ * P_ * H_);
    cudaMemsetAsync(pg, 0, sizeof(unsigned));
    cudaMemsetAsync(ptc, 0, sizeof(unsigned) * NPHASE);

    // biases (fp32 concat)
    cudaMemcpyAsync((float*)pb, b1, sizeof(float) * NG, cudaMemcpyDeviceToDevice);
    cudaMemcpyAsync((float*)pb + NG, bo1, sizeof(float) * H_, cudaMemcpyDeviceToDevice);
    cudaMemcpyAsync((float*)pb + NJ, b2, sizeof(float) * NG, cudaMemcpyDeviceToDevice);
    cudaMemcpyAsync((float*)pb + NJ + NG, bo2, sizeof(float) * H_, cudaMemcpyDeviceToDevice);

    // weight conversion to fp16
    {
        size_t ng = (size_t)P_ * KG * G3H;
        unsigned gb = (unsigned)((ng + 255) / 256);
        convert_wg<<<gb, 256>>>(Wh1, Wx1, (fp16*)pwg);
        convert_wg<<<gb, 256>>>(Wh2, Wx2, (fp16*)pwg + ng);
        unsigned ob = (KO * H_ + 255) / 256;
        convert_wo<<<ob, 256>>>(Who1, Wxo1, (fp16*)pwo);
        convert_wo<<<ob, 256>>>(Who2, Wxo2, (fp16*)pwo + KO * H_);
    }

    {
        size_t nf4 = (size_t)P_ * B_ * T_ * 32;
        transpose_x<<<(unsigned)((nf4 + 255) / 256), 256>>>(x);
    }

    int sms = 0, occ = 0;
    if (cudaDeviceGetAttribute(&sms, cudaDevAttrMultiProcessorCount, 0) != cudaSuccess
        || sms <= 0) sms = 148;
    if (cudaOccupancyMaxActiveBlocksPerMultiprocessor(&occ, recurrent_kernel, 128, 0)
        != cudaSuccess || occ <= 0) occ = 2;
    int nblk = sms * occ;
    if (nblk > NTILES) nblk = NTILES;
    recurrent_kernel<<<nblk, 128>>>(nblk);

    classifier<<<B_, 64>>>(Wfc, bfc, out);
}